// round 1
// baseline (speedup 1.0000x reference)
#include <cuda_runtime.h>

// IntensityTransform: out[b,h,w,c] = it[b, clip(round(255*im[b,h,w,c]),0,255), c]
// im: [16,512,512,3] f32, it: [16,256,3] f32, out: [16,512,512,3] f32
//
// HBM-bound streaming gather. float4 vectorized, per-batch LUT in smem.

#define B_DIM 16
#define HWC   (512 * 512 * 3)          // 786432 elements per batch
#define NVEC  (HWC / 4)                // 196608 float4 per batch
#define THREADS 256
#define BLOCKS_PER_B 96
#define ITERS (NVEC / (THREADS * BLOCKS_PER_B))   // 196608 / 24576 = 8

__global__ __launch_bounds__(THREADS)
void intensity_transform_kernel(const float* __restrict__ im,
                                const float* __restrict__ it,
                                float* __restrict__ out)
{
    __shared__ float lut[256 * 3];   // 3 KB: this batch's LUT, layout [idx*3 + c]

    const int b = blockIdx.y;

    // Stage LUT for batch b into shared memory (768 floats, 3 per thread)
    {
        const float* it_b = it + (size_t)b * (256 * 3);
        #pragma unroll
        for (int k = 0; k < 3; k++) {
            int i = threadIdx.x + k * THREADS;
            lut[i] = it_b[i];
        }
    }
    __syncthreads();

    const float4* __restrict__ imv  = (const float4*)(im  + (size_t)b * HWC);
    float4*       __restrict__ outv = (float4*)      (out + (size_t)b * HWC);

    const int tid0 = blockIdx.x * THREADS + threadIdx.x;

    #pragma unroll
    for (int k = 0; k < ITERS; k++) {
        const int j = tid0 + k * (THREADS * BLOCKS_PER_B);

        float4 v = imv[j];

        // channel of lane 0: (4*j) % 3 == j % 3  (since 4 ≡ 1 mod 3)
        int c0 = j % 3;
        int c1 = c0 + 1; if (c1 == 3) c1 = 0;
        int c2 = c1 + 1; if (c2 == 3) c2 = 0;
        // lane 3 channel == c0

        // round-half-to-even matches jnp.round exactly
        int i0 = __float2int_rn(255.0f * v.x);
        int i1 = __float2int_rn(255.0f * v.y);
        int i2 = __float2int_rn(255.0f * v.z);
        int i3 = __float2int_rn(255.0f * v.w);

        i0 = min(max(i0, 0), 255);
        i1 = min(max(i1, 0), 255);
        i2 = min(max(i2, 0), 255);
        i3 = min(max(i3, 0), 255);

        float4 r;
        r.x = lut[i0 * 3 + c0];
        r.y = lut[i1 * 3 + c1];
        r.z = lut[i2 * 3 + c2];
        r.w = lut[i3 * 3 + c0];

        outv[j] = r;
    }
}

extern "C" void kernel_launch(void* const* d_in, const int* in_sizes, int n_in,
                              void* d_out, int out_size)
{
    const float* im = (const float*)d_in[0];   // [16,512,512,3]
    const float* it = (const float*)d_in[1];   // [16,256,3]
    float* out = (float*)d_out;

    dim3 grid(BLOCKS_PER_B, B_DIM);
    intensity_transform_kernel<<<grid, THREADS>>>(im, it, out);
}

// round 3
// speedup vs baseline: 1.0587x; 1.0587x over previous
#include <cuda_runtime.h>

// IntensityTransform: out[b,h,w,c] = it[b, clip(round(255*im[b,h,w,c]),0,255), c]
// im: [16,512,512,3] f32, it: [16,256,3] f32, out: [16,512,512,3] f32
//
// L1-bound streaming gather. float4 vectorized; 8x bank-privatized LUT in smem
// to cut LDS conflict replays; __stcs output to preserve L2 residency of input.

#define B_DIM 16
#define HWC   (512 * 512 * 3)                    // 786432 elements per batch
#define NVEC  (HWC / 4)                          // 196608 float4 per batch
#define THREADS 256
#define BLOCKS_PER_B 48
#define STRIDE (THREADS * BLOCKS_PER_B)          // 12288 (divisible by 3)
#define ITERS (NVEC / STRIDE)                    // 16
#define REP 8                                    // LUT replication factor

__global__ __launch_bounds__(THREADS)
void intensity_transform_kernel(const float* __restrict__ im,
                                const float* __restrict__ it,
                                float* __restrict__ out)
{
    // 768 LUT entries x 8 replicas = 24 KB. Entry e, replica r at [e*8 + r].
    // Bank(addr) = 8*(e&3) + r  -> lanes only conflict within their own
    // 4-lane replica group, and only when e == e' (mod 4).
    __shared__ float lut[768 * REP];

    const int b = blockIdx.y;

    // Stage replicated LUT: 768 entries / 256 threads = 3 per thread,
    // each broadcast-written as two float4 (32B-aligned since e*8*4B = 32B*e).
    {
        const float* it_b = it + (size_t)b * (256 * 3);
        #pragma unroll
        for (int k = 0; k < 3; k++) {
            int e = threadIdx.x + k * THREADS;
            float v = it_b[e];
            float4 vv = make_float4(v, v, v, v);
            *reinterpret_cast<float4*>(&lut[e * REP])     = vv;
            *reinterpret_cast<float4*>(&lut[e * REP + 4]) = vv;
        }
    }
    __syncthreads();

    const int r = (threadIdx.x >> 2) & (REP - 1);   // replica for this lane

    const float4* __restrict__ imv  = (const float4*)(im  + (size_t)b * HWC);
    float4*       __restrict__ outv = (float4*)      (out + (size_t)b * HWC);

    const int tid0 = blockIdx.x * THREADS + threadIdx.x;

    // STRIDE % 3 == 0  ->  channel pattern is loop-invariant per thread.
    // channel of lane 0 of float4 j: (4*j) % 3 == j % 3.
    const int c0 = tid0 % 3;
    int c1 = c0 + 1; if (c1 == 3) c1 = 0;
    int c2 = c1 + 1; if (c2 == 3) c2 = 0;
    // lane 3 channel == c0

    #pragma unroll 4
    for (int k = 0; k < ITERS; k++) {
        const int j = tid0 + k * STRIDE;

        float4 v = imv[j];

        // round-half-to-even matches jnp.round exactly
        int i0 = __float2int_rn(255.0f * v.x);
        int i1 = __float2int_rn(255.0f * v.y);
        int i2 = __float2int_rn(255.0f * v.z);
        int i3 = __float2int_rn(255.0f * v.w);

        i0 = min(max(i0, 0), 255);
        i1 = min(max(i1, 0), 255);
        i2 = min(max(i2, 0), 255);
        i3 = min(max(i3, 0), 255);

        float4 o;
        o.x = lut[((i0 * 3 + c0) << 3) + r];
        o.y = lut[((i1 * 3 + c1) << 3) + r];
        o.z = lut[((i2 * 3 + c2) << 3) + r];
        o.w = lut[((i3 * 3 + c0) << 3) + r];

        // streaming store: don't let output evict the L2-resident input
        __stcs(&outv[j], o);
    }
}

extern "C" void kernel_launch(void* const* d_in, const int* in_sizes, int n_in,
                              void* d_out, int out_size)
{
    const float* im = (const float*)d_in[0];   // [16,512,512,3]
    const float* it = (const float*)d_in[1];   // [16,256,3]
    float* out = (float*)d_out;

    dim3 grid(BLOCKS_PER_B, B_DIM);
    intensity_transform_kernel<<<grid, THREADS>>>(im, it, out);
}